// round 1
// baseline (speedup 1.0000x reference)
#include <cuda_runtime.h>
#include <cuda_bf16.h>

// Problem constants (fixed for this dataset instance)
#define EMAX 1000000
#define DDIM 128
#define NMAX 200000
#define BMAX 512
#define NRMAX 481      // 2R+1
#define TMAX 100000

// ---------------- device scratch (static globals; no allocation) ----------------
__device__ float g_U[NMAX * DDIM];        // hidden @ Ws
__device__ float g_Vr[NRMAX * DDIM];      // rel_table @ Wr
__device__ float g_Qb[BMAX * DDIM];       // rel_table[query_rel+1] @ Wqr_w + b
__device__ float g_alpha[EMAX];           // per-edge gate
__device__ float g_AGG[TMAX * DDIM];      // segment sums
__device__ int   g_segcnt[TMAX];
__device__ int   g_segstart[TMAX + 1];
__device__ int   g_cursor[TMAX];
__device__ int   g_part[256];
__device__ int   g_perm[EMAX];

// ---------------- counting sort of edges by tail_index ----------------
__global__ void k_zero_int(int* p, int n) {
    int i = blockIdx.x * blockDim.x + threadIdx.x;
    if (i < n) p[i] = 0;
}

__global__ void k_hist(const int* __restrict__ tail, int E) {
    int e = blockIdx.x * blockDim.x + threadIdx.x;
    if (e < E) atomicAdd(&g_segcnt[tail[e]], 1);
}

__global__ void k_scanA(int T) {
    __shared__ int s[1024];
    int i = blockIdx.x * 1024 + threadIdx.x;
    int v = (i < T) ? g_segcnt[i] : 0;
    s[threadIdx.x] = v;
    __syncthreads();
    for (int off = 1; off < 1024; off <<= 1) {
        int x = (threadIdx.x >= off) ? s[threadIdx.x - off] : 0;
        __syncthreads();
        s[threadIdx.x] += x;
        __syncthreads();
    }
    if (i < T) g_segstart[i] = s[threadIdx.x] - v;  // block-local exclusive
    if (threadIdx.x == 1023) g_part[blockIdx.x] = s[1023];
}

__global__ void k_scanB(int nb) {
    if (threadIdx.x == 0 && blockIdx.x == 0) {
        int run = 0;
        for (int b = 0; b < nb; b++) { int c = g_part[b]; g_part[b] = run; run += c; }
    }
}

__global__ void k_scanC(int T, int E) {
    int i = blockIdx.x * 1024 + threadIdx.x;
    if (i < T) {
        int v = g_segstart[i] + g_part[blockIdx.x];
        g_segstart[i] = v;
        g_cursor[i] = v;
    }
    if (i == 0) g_segstart[T] = E;
}

__global__ void k_scatter(const int* __restrict__ tail, int E) {
    int e = blockIdx.x * blockDim.x + threadIdx.x;
    if (e < E) {
        int p = atomicAdd(&g_cursor[tail[e]], 1);
        g_perm[p] = e;
    }
}

// ---------------- tiny projections ----------------
__global__ void k_vr(const float* __restrict__ rel, const float* __restrict__ Wr) {
    __shared__ float row[DDIM];
    int r = blockIdx.x, j = threadIdx.x;
    row[j] = rel[r * DDIM + j];
    __syncthreads();
    float s = 0.f;
    #pragma unroll 8
    for (int k = 0; k < DDIM; k++) s = fmaf(row[k], Wr[k * DDIM + j], s);
    g_Vr[r * DDIM + j] = s;
}

__global__ void k_qb(const float* __restrict__ rel, const float* __restrict__ W,
                     const float* __restrict__ bias, const int* __restrict__ qrel) {
    __shared__ float row[DDIM];
    int b = blockIdx.x, j = threadIdx.x;
    int r = qrel[b] + 1;
    row[j] = rel[r * DDIM + j];
    __syncthreads();
    float s = bias[j];
    #pragma unroll 8
    for (int k = 0; k < DDIM; k++) s = fmaf(row[k], W[k * DDIM + j], s);
    g_Qb[b * DDIM + j] = s;
}

// ---------------- fp32 GEMM: C[M,128] = A[M,128] @ B[128,128] ----------------
__global__ __launch_bounds__(256, 1)
void gemm_k128(const float* __restrict__ A, const float* __restrict__ B,
               float* __restrict__ C, int M) {
    extern __shared__ float sm[];
    float* As = sm;            // [128][128] row-major (row, k)
    float* Bs = sm + 16384;    // [128][128] (k, col)
    const int tid = threadIdx.x;
    const int rbase = blockIdx.x * 128;

    const float4* B4 = (const float4*)B;
    const float4* A4 = (const float4*)A;
    float4* Bs4 = (float4*)Bs;
    float4* As4 = (float4*)As;

    #pragma unroll
    for (int it = 0; it < 16; ++it) {
        int f = it * 256 + tid;          // float4 index, 0..4095
        Bs4[f] = B4[f];
        int row = f >> 5, c4 = f & 31;
        int gr = rbase + row;
        float4 v = make_float4(0.f, 0.f, 0.f, 0.f);
        if (gr < M) v = A4[gr * 32 + c4];
        As4[f] = v;
    }
    __syncthreads();

    const int ty = tid >> 4, tx = tid & 15;   // 16x16 thread grid; 8x8 outputs each
    float acc[8][8];
    #pragma unroll
    for (int i = 0; i < 8; i++)
        #pragma unroll
        for (int j = 0; j < 8; j++) acc[i][j] = 0.f;

    for (int k0 = 0; k0 < 128; k0 += 4) {
        float4 a4[8];
        #pragma unroll
        for (int i = 0; i < 8; i++) a4[i] = As4[(ty * 8 + i) * 32 + (k0 >> 2)];
        #pragma unroll
        for (int dk = 0; dk < 4; dk++) {
            float4 b0 = Bs4[(k0 + dk) * 32 + tx * 2];
            float4 b1 = Bs4[(k0 + dk) * 32 + tx * 2 + 1];
            float bb[8] = {b0.x, b0.y, b0.z, b0.w, b1.x, b1.y, b1.z, b1.w};
            #pragma unroll
            for (int i = 0; i < 8; i++) {
                float av = (dk == 0) ? a4[i].x : (dk == 1) ? a4[i].y : (dk == 2) ? a4[i].z : a4[i].w;
                #pragma unroll
                for (int j = 0; j < 8; j++) acc[i][j] = fmaf(av, bb[j], acc[i][j]);
            }
        }
    }

    float4* C4 = (float4*)C;
    #pragma unroll
    for (int i = 0; i < 8; i++) {
        int gr = rbase + ty * 8 + i;
        if (gr < M) {
            float4 o0 = make_float4(acc[i][0], acc[i][1], acc[i][2], acc[i][3]);
            float4 o1 = make_float4(acc[i][4], acc[i][5], acc[i][6], acc[i][7]);
            C4[gr * 32 + tx * 2] = o0;
            C4[gr * 32 + tx * 2 + 1] = o1;
        }
    }
}

// ---------------- per-edge gate: alpha[e] = sigmoid(wa . relu(U[n]+Vr[r+1]+Qb[b]) + wa_b)
__global__ __launch_bounds__(256)
void k_alpha(const int* __restrict__ facts, const float* __restrict__ wa_w,
             const float* __restrict__ wa_b, int E) {
    int wid = (blockIdx.x * blockDim.x + threadIdx.x) >> 5;
    int lane = threadIdx.x & 31;
    if (wid >= E) return;
    int base = wid * 6;
    int b = facts[base + 0];
    int n = facts[base + 1];
    int r = facts[base + 3];

    const float4* U4 = (const float4*)g_U;
    const float4* V4 = (const float4*)g_Vr;
    const float4* Q4 = (const float4*)g_Qb;
    const float4* W4 = (const float4*)wa_w;

    float4 u = U4[n * 32 + lane];
    float4 v = V4[(r + 1) * 32 + lane];
    float4 q = Q4[b * 32 + lane];
    float4 w = W4[lane];

    float s = fmaxf(u.x + v.x + q.x, 0.f) * w.x
            + fmaxf(u.y + v.y + q.y, 0.f) * w.y
            + fmaxf(u.z + v.z + q.z, 0.f) * w.z
            + fmaxf(u.w + v.w + q.w, 0.f) * w.w;
    s += __shfl_xor_sync(0xffffffffu, s, 16);
    s += __shfl_xor_sync(0xffffffffu, s, 8);
    s += __shfl_xor_sync(0xffffffffu, s, 4);
    s += __shfl_xor_sync(0xffffffffu, s, 2);
    s += __shfl_xor_sync(0xffffffffu, s, 1);
    if (lane == 0) {
        float x = s + wa_b[0];
        g_alpha[wid] = 1.f / (1.f + __expf(-x));
    }
}

// ---------------- per-segment aggregation (no atomics) ----------------
__global__ __launch_bounds__(256)
void k_agg(const int* __restrict__ facts, const float* __restrict__ hidden,
           const float* __restrict__ rel, int T) {
    int seg = (blockIdx.x * blockDim.x + threadIdx.x) >> 5;
    int lane = threadIdx.x & 31;
    if (seg >= T) return;
    int s0 = g_segstart[seg];
    int s1 = g_segstart[seg + 1];

    const float4* H4 = (const float4*)hidden;
    const float4* R4 = (const float4*)rel;
    float4 acc = make_float4(0.f, 0.f, 0.f, 0.f);

    for (int k = s0; k < s1; k++) {
        int e = g_perm[k];                // uniform across warp (broadcast)
        float a = g_alpha[e];
        int n = facts[e * 6 + 1];
        int r = facts[e * 6 + 3];
        float4 h = H4[n * 32 + lane];
        float4 hr = R4[(r + 1) * 32 + lane];
        acc.x = fmaf(a, h.x + hr.x, acc.x);
        acc.y = fmaf(a, h.y + hr.y, acc.y);
        acc.z = fmaf(a, h.z + hr.z, acc.z);
        acc.w = fmaf(a, h.w + hr.w, acc.w);
    }
    ((float4*)g_AGG)[seg * 32 + lane] = acc;
}

// ---------------- launch ----------------
extern "C" void kernel_launch(void* const* d_in, const int* in_sizes, int n_in,
                              void* d_out, int out_size) {
    const float* hidden    = (const float*)d_in[0];
    const float* rel_table = (const float*)d_in[1];
    const float* Ws        = (const float*)d_in[2];
    const float* Wr        = (const float*)d_in[3];
    const float* Wqr_w     = (const float*)d_in[4];
    const float* Wqr_b     = (const float*)d_in[5];
    const float* wa_w      = (const float*)d_in[6];
    const float* wa_b      = (const float*)d_in[7];
    const float* Wh        = (const float*)d_in[8];
    const int*   query_rel = (const int*)d_in[9];
    const int*   facts     = (const int*)d_in[10];
    const int*   tail      = (const int*)d_in[11];
    // d_in[12] = tail_nodes (arange, unused beyond its length)

    const int E  = in_sizes[11];          // 1,000,000
    const int T  = in_sizes[12];          // 100,000
    const int N  = in_sizes[0] / DDIM;    // 200,000
    const int B  = in_sizes[9];           // 512
    const int NR = in_sizes[1] / DDIM;    // 481
    float* out = (float*)d_out;

    // opt-in to 128KB dynamic smem for the GEMM (idempotent, called every time)
    cudaFuncSetAttribute((const void*)gemm_k128,
                         cudaFuncAttributeMaxDynamicSharedMemorySize, 131072);

    float* d_U;   cudaGetSymbolAddress((void**)&d_U, g_U);
    float* d_AGG; cudaGetSymbolAddress((void**)&d_AGG, g_AGG);
    int* d_segcnt; cudaGetSymbolAddress((void**)&d_segcnt, g_segcnt);

    // 1) counting sort of edges by tail segment
    k_zero_int<<<(T + 255) / 256, 256>>>(d_segcnt, T);
    k_hist<<<(E + 255) / 256, 256>>>(tail, E);
    int nb = (T + 1023) / 1024;
    k_scanA<<<nb, 1024>>>(T);
    k_scanB<<<1, 32>>>(nb);
    k_scanC<<<nb, 1024>>>(T, E);
    k_scatter<<<(E + 255) / 256, 256>>>(tail, E);

    // 2) hoisted projections
    k_vr<<<NR, DDIM>>>(rel_table, Wr);
    k_qb<<<B, DDIM>>>(rel_table, Wqr_w, Wqr_b, query_rel);
    gemm_k128<<<(N + 127) / 128, 256, 131072>>>(hidden, Ws, d_U, N);

    // 3) per-edge gates
    k_alpha<<<(E + 7) / 8, 256>>>(facts, wa_w, wa_b, E);

    // 4) segment aggregation (one warp per segment, register accumulation)
    k_agg<<<(T + 7) / 8, 256>>>(facts, hidden, rel_table, T);

    // 5) output projection
    gemm_k128<<<(T + 127) / 128, 256, 131072>>>(d_AGG, Wh, out, T);
}

// round 3
// speedup vs baseline: 1.3259x; 1.3259x over previous
#include <cuda_runtime.h>
#include <cuda_bf16.h>
#include <cstdint>

// Problem constants (fixed for this dataset instance)
#define EMAX 1000000
#define DDIM 128
#define NMAX 200000
#define BMAX 512
#define NRMAX 481      // 2R+1
#define TMAX 100000

// ---------------- device scratch (static globals; no allocation) ----------------
__device__ float g_U[NMAX * DDIM];        // hidden @ Ws
__device__ float g_Vr[NRMAX * DDIM];      // rel_table @ Wr
__device__ float g_Qb[BMAX * DDIM];       // rel_table[query_rel+1] @ Wqr_w + b
__device__ float g_alpha[EMAX];           // per-edge gate
__device__ float g_AGG[TMAX * DDIM];      // segment sums
__device__ int   g_segcnt[TMAX];
__device__ int   g_segstart[TMAX + 1];
__device__ int   g_cursor[TMAX];
__device__ int   g_part[256];
__device__ int   g_perm[EMAX];
// pre-split transposed weight images Wt[n][k] (bf16 hi/lo, packed as uint32 = 2 halves)
__device__ uint32_t g_WsHi[8192];
__device__ uint32_t g_WsLo[8192];
__device__ uint32_t g_WhHi[8192];
__device__ uint32_t g_WhLo[8192];

__device__ __forceinline__ uint32_t smem_u32(const void* p) {
    uint32_t a;
    asm("{ .reg .u64 t; cvta.to.shared.u64 t, %1; cvt.u32.u64 %0, t; }" : "=r"(a) : "l"(p));
    return a;
}
__device__ __forceinline__ uint32_t b2u(__nv_bfloat162 h) { return *reinterpret_cast<uint32_t*>(&h); }

__device__ __forceinline__ void ldsm_x4(uint32_t addr, uint32_t& r0, uint32_t& r1,
                                        uint32_t& r2, uint32_t& r3) {
    asm volatile("ldmatrix.sync.aligned.m8n8.x4.shared.b16 {%0,%1,%2,%3}, [%4];"
                 : "=r"(r0), "=r"(r1), "=r"(r2), "=r"(r3) : "r"(addr));
}
__device__ __forceinline__ void mma16816(float* d, const uint32_t* a, const uint32_t* b) {
    asm volatile(
        "mma.sync.aligned.m16n8k16.row.col.f32.bf16.bf16.f32 "
        "{%0,%1,%2,%3}, {%4,%5,%6,%7}, {%8,%9}, {%0,%1,%2,%3};"
        : "+f"(d[0]), "+f"(d[1]), "+f"(d[2]), "+f"(d[3])
        : "r"(a[0]), "r"(a[1]), "r"(a[2]), "r"(a[3]), "r"(b[0]), "r"(b[1]));
}

// ---------------- counting sort of edges by tail_index ----------------
__global__ void k_zero_int(int* p, int n) {
    int i = blockIdx.x * blockDim.x + threadIdx.x;
    if (i < n) p[i] = 0;
}

__global__ void k_hist(const int* __restrict__ tail, int E) {
    int e = blockIdx.x * blockDim.x + threadIdx.x;
    if (e < E) atomicAdd(&g_segcnt[tail[e]], 1);
}

__global__ void k_scanA(int T) {
    __shared__ int s[1024];
    int i = blockIdx.x * 1024 + threadIdx.x;
    int v = (i < T) ? g_segcnt[i] : 0;
    s[threadIdx.x] = v;
    __syncthreads();
    for (int off = 1; off < 1024; off <<= 1) {
        int x = (threadIdx.x >= off) ? s[threadIdx.x - off] : 0;
        __syncthreads();
        s[threadIdx.x] += x;
        __syncthreads();
    }
    if (i < T) g_segstart[i] = s[threadIdx.x] - v;  // block-local exclusive
    if (threadIdx.x == 1023) g_part[blockIdx.x] = s[1023];
}

__global__ void k_scanB(int nb) {
    __shared__ int s[128];
    int i = threadIdx.x;
    int v = (i < nb) ? g_part[i] : 0;
    s[i] = v;
    __syncthreads();
    for (int off = 1; off < 128; off <<= 1) {
        int x = (i >= off) ? s[i - off] : 0;
        __syncthreads();
        s[i] += x;
        __syncthreads();
    }
    if (i < nb) g_part[i] = s[i] - v;  // exclusive
}

__global__ void k_scanC(int T, int E) {
    int i = blockIdx.x * 1024 + threadIdx.x;
    if (i < T) {
        int v = g_segstart[i] + g_part[blockIdx.x];
        g_segstart[i] = v;
        g_cursor[i] = v;
    }
    if (i == 0) g_segstart[T] = E;
}

__global__ void k_scatter(const int* __restrict__ tail, int E) {
    int e = blockIdx.x * blockDim.x + threadIdx.x;
    if (e < E) {
        int p = atomicAdd(&g_cursor[tail[e]], 1);
        g_perm[p] = e;
    }
}

// ---------------- tiny projections ----------------
__global__ void k_vr(const float* __restrict__ rel, const float* __restrict__ Wr) {
    __shared__ float row[DDIM];
    int r = blockIdx.x, j = threadIdx.x;
    row[j] = rel[r * DDIM + j];
    __syncthreads();
    float s = 0.f;
    #pragma unroll 8
    for (int k = 0; k < DDIM; k++) s = fmaf(row[k], Wr[k * DDIM + j], s);
    g_Vr[r * DDIM + j] = s;
}

__global__ void k_qb(const float* __restrict__ rel, const float* __restrict__ W,
                     const float* __restrict__ bias, const int* __restrict__ qrel) {
    __shared__ float row[DDIM];
    int b = blockIdx.x, j = threadIdx.x;
    int r = qrel[b] + 1;
    row[j] = rel[r * DDIM + j];
    __syncthreads();
    float s = bias[j];
    #pragma unroll 8
    for (int k = 0; k < DDIM; k++) s = fmaf(row[k], W[k * DDIM + j], s);
    g_Qb[b * DDIM + j] = s;
}

// ---------------- weight prep: split fp32 W[k][n] -> bf16 hi/lo, transposed Wt[n][k] ----------------
__global__ void k_prep_w(const float* __restrict__ W,
                         uint32_t* __restrict__ outHi, uint32_t* __restrict__ outLo) {
    int n = threadIdx.x;  // 128 threads, one output row (N dim) each
    #pragma unroll 4
    for (int k = 0; k < 128; k += 2) {
        float w0 = W[(k + 0) * 128 + n];
        float w1 = W[(k + 1) * 128 + n];
        __nv_bfloat162 hi = __floats2bfloat162_rn(w0, w1);
        float l0 = w0 - __bfloat162float(hi.x);
        float l1 = w1 - __bfloat162float(hi.y);
        __nv_bfloat162 lo = __floats2bfloat162_rn(l0, l1);
        outHi[n * 64 + (k >> 1)] = b2u(hi);
        outLo[n * 64 + (k >> 1)] = b2u(lo);
    }
}

// ---------------- bf16x3 tensor-core GEMM via mma.sync: C[M,128] = A[M,128] @ W[128,128]
// D = Ahi*Bhi + Ahi*Blo + Alo*Bhi (fp32 accum). B pre-split/transposed by k_prep_w.
#define BSTRIDE 136                       // halves per smem row (272B -> conflict-free ldmatrix)
#define SMEM_GEMM (4 * 128 * BSTRIDE * 2) // 139264 bytes

__global__ __launch_bounds__(256, 1)
void gemm_mma(const float* __restrict__ A, const uint32_t* __restrict__ BHi,
              const uint32_t* __restrict__ BLo, float* __restrict__ C, int M) {
    extern __shared__ __align__(16) uint8_t smraw[];
    __nv_bfloat16* sAhi = (__nv_bfloat16*)smraw;
    __nv_bfloat16* sAlo = sAhi + 128 * BSTRIDE;
    __nv_bfloat16* sBhi = sAlo + 128 * BSTRIDE;
    __nv_bfloat16* sBlo = sBhi + 128 * BSTRIDE;

    const int tid = threadIdx.x;
    const int w = tid >> 5, lane = tid & 31;
    const int rbase = blockIdx.x * 128;

    // B: copy pre-split images into padded smem rows
    const uint4* bh4 = (const uint4*)BHi;
    const uint4* bl4 = (const uint4*)BLo;
    #pragma unroll
    for (int it = 0; it < 8; it++) {
        int i = it * 256 + tid;           // 2048 uint4 per matrix
        int n = i >> 4, c = i & 15;
        *(uint4*)(sBhi + n * BSTRIDE + c * 8) = bh4[i];
        *(uint4*)(sBlo + n * BSTRIDE + c * 8) = bl4[i];
    }
    // A: coalesced fp32 load -> hi/lo bf16 split -> padded smem
    const float4* A4 = (const float4*)A;
    #pragma unroll
    for (int it = 0; it < 16; it++) {
        int f = it * 256 + tid;           // 4096 float4
        int row = f >> 5, c4 = f & 31;
        int gr = rbase + row;
        float4 v = make_float4(0.f, 0.f, 0.f, 0.f);
        if (gr < M) v = A4[gr * 32 + c4];
        __nv_bfloat162 h01 = __floats2bfloat162_rn(v.x, v.y);
        __nv_bfloat162 h23 = __floats2bfloat162_rn(v.z, v.w);
        __nv_bfloat162 l01 = __floats2bfloat162_rn(v.x - __bfloat162float(h01.x),
                                                   v.y - __bfloat162float(h01.y));
        __nv_bfloat162 l23 = __floats2bfloat162_rn(v.z - __bfloat162float(h23.x),
                                                   v.w - __bfloat162float(h23.y));
        *(uint2*)(sAhi + row * BSTRIDE + c4 * 4) = make_uint2(b2u(h01), b2u(h23));
        *(uint2*)(sAlo + row * BSTRIDE + c4 * 4) = make_uint2(b2u(l01), b2u(l23));
    }
    __syncthreads();

    // ldmatrix per-lane base addresses
    const int quad = lane >> 3, l = lane & 7;
    const uint32_t aoff = (uint32_t)(((w * 16 + (quad & 1) * 8 + l) * BSTRIDE + (quad >> 1) * 8) * 2);
    const uint32_t boff = (uint32_t)((((quad >> 1) * 8 + l) * BSTRIDE + (quad & 1) * 8) * 2);
    const uint32_t aHiA = smem_u32(sAhi) + aoff;
    const uint32_t aLoA = smem_u32(sAlo) + aoff;
    const uint32_t bHiA = smem_u32(sBhi) + boff;
    const uint32_t bLoA = smem_u32(sBlo) + boff;

    float acc[16][4];
    #pragma unroll
    for (int i = 0; i < 16; i++)
        #pragma unroll
        for (int j = 0; j < 4; j++) acc[i][j] = 0.f;

    #pragma unroll 1
    for (int ks = 0; ks < 8; ks++) {
        uint32_t ah[4], al[4];
        ldsm_x4(aHiA + ks * 32, ah[0], ah[1], ah[2], ah[3]);
        ldsm_x4(aLoA + ks * 32, al[0], al[1], al[2], al[3]);
        #pragma unroll
        for (int np = 0; np < 8; np++) {
            uint32_t bh[4], bl[4];
            uint32_t o = (uint32_t)(np * 16 * BSTRIDE * 2 + ks * 32);
            ldsm_x4(bHiA + o, bh[0], bh[1], bh[2], bh[3]);
            ldsm_x4(bLoA + o, bl[0], bl[1], bl[2], bl[3]);
            mma16816(acc[2 * np],     ah, bh);
            mma16816(acc[2 * np + 1], ah, bh + 2);
            mma16816(acc[2 * np],     ah, bl);
            mma16816(acc[2 * np + 1], ah, bl + 2);
            mma16816(acc[2 * np],     al, bh);
            mma16816(acc[2 * np + 1], al, bh + 2);
        }
    }

    // Epilogue: direct float2 stores (thread t of warp w: rows w*16 + t/4 (+8), col pair (t%4)*2)
    const int r0 = rbase + w * 16 + (lane >> 2);
    const int cn = (lane & 3) * 2;
    #pragma unroll
    for (int nt = 0; nt < 16; nt++) {
        if (r0 < M)     *(float2*)&C[r0 * 128 + nt * 8 + cn]       = make_float2(acc[nt][0], acc[nt][1]);
        if (r0 + 8 < M) *(float2*)&C[(r0 + 8) * 128 + nt * 8 + cn] = make_float2(acc[nt][2], acc[nt][3]);
    }
}

// ---------------- per-edge gate: alpha[e] = sigmoid(wa . relu(U[n]+Vr[r+1]+Qb[b]) + wa_b)
__global__ __launch_bounds__(256)
void k_alpha(const int* __restrict__ facts, const float* __restrict__ wa_w,
             const float* __restrict__ wa_b, int E) {
    int wid = (blockIdx.x * blockDim.x + threadIdx.x) >> 5;
    int lane = threadIdx.x & 31;
    if (wid >= E) return;
    int base = wid * 6;
    int b = facts[base + 0];
    int n = facts[base + 1];
    int r = facts[base + 3];

    const float4* U4 = (const float4*)g_U;
    const float4* V4 = (const float4*)g_Vr;
    const float4* Q4 = (const float4*)g_Qb;
    const float4* W4 = (const float4*)wa_w;

    float4 u = U4[n * 32 + lane];
    float4 v = V4[(r + 1) * 32 + lane];
    float4 q = Q4[b * 32 + lane];
    float4 w = W4[lane];

    float s = fmaxf(u.x + v.x + q.x, 0.f) * w.x
            + fmaxf(u.y + v.y + q.y, 0.f) * w.y
            + fmaxf(u.z + v.z + q.z, 0.f) * w.z
            + fmaxf(u.w + v.w + q.w, 0.f) * w.w;
    s += __shfl_xor_sync(0xffffffffu, s, 16);
    s += __shfl_xor_sync(0xffffffffu, s, 8);
    s += __shfl_xor_sync(0xffffffffu, s, 4);
    s += __shfl_xor_sync(0xffffffffu, s, 2);
    s += __shfl_xor_sync(0xffffffffu, s, 1);
    if (lane == 0) {
        float x = s + wa_b[0];
        g_alpha[wid] = 1.f / (1.f + __expf(-x));
    }
}

// ---------------- per-segment aggregation (no atomics) ----------------
__global__ __launch_bounds__(256)
void k_agg(const int* __restrict__ facts, const float* __restrict__ hidden,
           const float* __restrict__ rel, int T) {
    int seg = (blockIdx.x * blockDim.x + threadIdx.x) >> 5;
    int lane = threadIdx.x & 31;
    if (seg >= T) return;
    int s0 = g_segstart[seg];
    int s1 = g_segstart[seg + 1];

    const float4* H4 = (const float4*)hidden;
    const float4* R4 = (const float4*)rel;
    float4 acc = make_float4(0.f, 0.f, 0.f, 0.f);

    for (int k = s0; k < s1; k++) {
        int e = g_perm[k];                // uniform across warp (broadcast)
        float a = g_alpha[e];
        int n = facts[e * 6 + 1];
        int r = facts[e * 6 + 3];
        float4 h = H4[n * 32 + lane];
        float4 hr = R4[(r + 1) * 32 + lane];
        acc.x = fmaf(a, h.x + hr.x, acc.x);
        acc.y = fmaf(a, h.y + hr.y, acc.y);
        acc.z = fmaf(a, h.z + hr.z, acc.z);
        acc.w = fmaf(a, h.w + hr.w, acc.w);
    }
    ((float4*)g_AGG)[seg * 32 + lane] = acc;
}

// ---------------- launch ----------------
extern "C" void kernel_launch(void* const* d_in, const int* in_sizes, int n_in,
                              void* d_out, int out_size) {
    const float* hidden    = (const float*)d_in[0];
    const float* rel_table = (const float*)d_in[1];
    const float* Ws        = (const float*)d_in[2];
    const float* Wr        = (const float*)d_in[3];
    const float* Wqr_w     = (const float*)d_in[4];
    const float* Wqr_b     = (const float*)d_in[5];
    const float* wa_w      = (const float*)d_in[6];
    const float* wa_b      = (const float*)d_in[7];
    const float* Wh        = (const float*)d_in[8];
    const int*   query_rel = (const int*)d_in[9];
    const int*   facts     = (const int*)d_in[10];
    const int*   tail      = (const int*)d_in[11];

    const int E  = in_sizes[11];          // 1,000,000
    const int T  = in_sizes[12];          // 100,000
    const int N  = in_sizes[0] / DDIM;    // 200,000
    const int B  = in_sizes[9];           // 512
    const int NR = in_sizes[1] / DDIM;    // 481
    float* out = (float*)d_out;

    cudaFuncSetAttribute((const void*)gemm_mma,
                         cudaFuncAttributeMaxDynamicSharedMemorySize, SMEM_GEMM);

    float* d_U;   cudaGetSymbolAddress((void**)&d_U, g_U);
    float* d_AGG; cudaGetSymbolAddress((void**)&d_AGG, g_AGG);
    int* d_segcnt; cudaGetSymbolAddress((void**)&d_segcnt, g_segcnt);
    uint32_t *d_WsHi, *d_WsLo, *d_WhHi, *d_WhLo;
    cudaGetSymbolAddress((void**)&d_WsHi, g_WsHi);
    cudaGetSymbolAddress((void**)&d_WsLo, g_WsLo);
    cudaGetSymbolAddress((void**)&d_WhHi, g_WhHi);
    cudaGetSymbolAddress((void**)&d_WhLo, g_WhLo);

    // 1) counting sort of edges by tail segment
    k_zero_int<<<(T + 255) / 256, 256>>>(d_segcnt, T);
    k_hist<<<(E + 255) / 256, 256>>>(tail, E);
    int nb = (T + 1023) / 1024;
    k_scanA<<<nb, 1024>>>(T);
    k_scanB<<<1, 128>>>(nb);
    k_scanC<<<nb, 1024>>>(T, E);
    k_scatter<<<(E + 255) / 256, 256>>>(tail, E);

    // 2) weight prep (bf16 split, transposed)
    k_prep_w<<<1, 128>>>(Ws, d_WsHi, d_WsLo);
    k_prep_w<<<1, 128>>>(Wh, d_WhHi, d_WhLo);

    // 3) hoisted projections
    k_vr<<<NR, DDIM>>>(rel_table, Wr);
    k_qb<<<B, DDIM>>>(rel_table, Wqr_w, Wqr_b, query_rel);
    gemm_mma<<<(N + 127) / 128, 256, SMEM_GEMM>>>(hidden, d_WsHi, d_WsLo, d_U, N);

    // 4) per-edge gates
    k_alpha<<<(E + 7) / 8, 256>>>(facts, wa_w, wa_b, E);

    // 5) segment aggregation (one warp per segment, register accumulation)
    k_agg<<<(T + 7) / 8, 256>>>(facts, hidden, rel_table, T);

    // 6) output projection
    gemm_mma<<<(T + 127) / 128, 256, SMEM_GEMM>>>(d_AGG, d_WhHi, d_WhLo, out, T);
}

// round 4
// speedup vs baseline: 1.4359x; 1.0830x over previous
#include <cuda_runtime.h>
#include <cuda_bf16.h>
#include <cstdint>

// Problem constants (fixed for this dataset instance)
#define EMAX 1000000
#define DDIM 128
#define NMAX 200000
#define BMAX 512
#define NRMAX 481      // 2R+1
#define TMAX 100000

// ---------------- device scratch (static globals; no allocation) ----------------
__device__ float g_U[NMAX * DDIM];        // hidden @ Ws
__device__ float g_Vr[NRMAX * DDIM];      // rel_table @ Wr
__device__ float g_Qb[BMAX * DDIM];       // rel_table[query_rel+1] @ Wqr_w + b
__device__ float g_alphaP[EMAX];          // per-edge gate, PERMUTED to sorted position
__device__ float g_AGG[TMAX * DDIM];      // segment sums
__device__ int   g_segcnt[TMAX];
__device__ int   g_segstart[TMAX + 1];
__device__ int   g_cursor[TMAX];
__device__ int   g_part[256];
__device__ int   g_pos[EMAX];             // edge -> sorted position
__device__ int2  g_edgeNR[EMAX];          // sorted-position -> (n, r+1)
// pre-split transposed weight images Wt[n][k] (bf16 hi/lo, packed as uint32 = 2 halves)
__device__ uint32_t g_WsHi[8192];
__device__ uint32_t g_WsLo[8192];
__device__ uint32_t g_WhHi[8192];
__device__ uint32_t g_WhLo[8192];

__device__ __forceinline__ uint32_t smem_u32(const void* p) {
    uint32_t a;
    asm("{ .reg .u64 t; cvta.to.shared.u64 t, %1; cvt.u32.u64 %0, t; }" : "=r"(a) : "l"(p));
    return a;
}
__device__ __forceinline__ uint32_t b2u(__nv_bfloat162 h) { return *reinterpret_cast<uint32_t*>(&h); }

__device__ __forceinline__ void ldsm_x4(uint32_t addr, uint32_t& r0, uint32_t& r1,
                                        uint32_t& r2, uint32_t& r3) {
    asm volatile("ldmatrix.sync.aligned.m8n8.x4.shared.b16 {%0,%1,%2,%3}, [%4];"
                 : "=r"(r0), "=r"(r1), "=r"(r2), "=r"(r3) : "r"(addr));
}
__device__ __forceinline__ void mma16816(float* d, const uint32_t* a, const uint32_t* b) {
    asm volatile(
        "mma.sync.aligned.m16n8k16.row.col.f32.bf16.bf16.f32 "
        "{%0,%1,%2,%3}, {%4,%5,%6,%7}, {%8,%9}, {%0,%1,%2,%3};"
        : "+f"(d[0]), "+f"(d[1]), "+f"(d[2]), "+f"(d[3])
        : "r"(a[0]), "r"(a[1]), "r"(a[2]), "r"(a[3]), "r"(b[0]), "r"(b[1]));
}

// ---------------- counting sort of edges by tail_index ----------------
__global__ void k_zero_int(int* p, int n) {
    int i = blockIdx.x * blockDim.x + threadIdx.x;
    if (i < n) p[i] = 0;
}

__global__ void k_hist(const int* __restrict__ tail, int E) {
    int e = blockIdx.x * blockDim.x + threadIdx.x;
    if (e < E) atomicAdd(&g_segcnt[tail[e]], 1);
}

__global__ void k_scanA(int T) {
    __shared__ int s[1024];
    int i = blockIdx.x * 1024 + threadIdx.x;
    int v = (i < T) ? g_segcnt[i] : 0;
    s[threadIdx.x] = v;
    __syncthreads();
    for (int off = 1; off < 1024; off <<= 1) {
        int x = (threadIdx.x >= off) ? s[threadIdx.x - off] : 0;
        __syncthreads();
        s[threadIdx.x] += x;
        __syncthreads();
    }
    if (i < T) g_segstart[i] = s[threadIdx.x] - v;  // block-local exclusive
    if (threadIdx.x == 1023) g_part[blockIdx.x] = s[1023];
}

__global__ void k_scanB(int nb) {
    __shared__ int s[128];
    int i = threadIdx.x;
    int v = (i < nb) ? g_part[i] : 0;
    s[i] = v;
    __syncthreads();
    for (int off = 1; off < 128; off <<= 1) {
        int x = (i >= off) ? s[i - off] : 0;
        __syncthreads();
        s[i] += x;
        __syncthreads();
    }
    if (i < nb) g_part[i] = s[i] - v;  // exclusive
}

__global__ void k_scanC(int T, int E) {
    int i = blockIdx.x * 1024 + threadIdx.x;
    if (i < T) {
        int v = g_segstart[i] + g_part[blockIdx.x];
        g_segstart[i] = v;
        g_cursor[i] = v;
    }
    if (i == 0) g_segstart[T] = E;
}

// scatter: also de-reference facts here (sequential read!) so k_agg needs no indirection
__global__ void k_scatter(const int* __restrict__ tail, const int* __restrict__ facts, int E) {
    int e = blockIdx.x * blockDim.x + threadIdx.x;
    if (e < E) {
        int2 bn = *(const int2*)(facts + e * 6);      // (b, n)
        int2 hr = *(const int2*)(facts + e * 6 + 2);  // (h, r)
        int p = atomicAdd(&g_cursor[tail[e]], 1);
        g_edgeNR[p] = make_int2(bn.y, hr.y + 1);
        g_pos[e] = p;
    }
}

// ---------------- tiny projections ----------------
__global__ void k_vr(const float* __restrict__ rel, const float* __restrict__ Wr) {
    __shared__ float row[DDIM];
    int r = blockIdx.x, j = threadIdx.x;
    row[j] = rel[r * DDIM + j];
    __syncthreads();
    float s = 0.f;
    #pragma unroll 8
    for (int k = 0; k < DDIM; k++) s = fmaf(row[k], Wr[k * DDIM + j], s);
    g_Vr[r * DDIM + j] = s;
}

__global__ void k_qb(const float* __restrict__ rel, const float* __restrict__ W,
                     const float* __restrict__ bias, const int* __restrict__ qrel) {
    __shared__ float row[DDIM];
    int b = blockIdx.x, j = threadIdx.x;
    int r = qrel[b] + 1;
    row[j] = rel[r * DDIM + j];
    __syncthreads();
    float s = bias[j];
    #pragma unroll 8
    for (int k = 0; k < DDIM; k++) s = fmaf(row[k], W[k * DDIM + j], s);
    g_Qb[b * DDIM + j] = s;
}

// ---------------- weight prep: split fp32 W[k][n] -> bf16 hi/lo, transposed Wt[n][k] ----------------
__global__ void k_prep_w(const float* __restrict__ W,
                         uint32_t* __restrict__ outHi, uint32_t* __restrict__ outLo) {
    int n = threadIdx.x;  // 128 threads, one output row (N dim) each
    #pragma unroll 4
    for (int k = 0; k < 128; k += 2) {
        float w0 = W[(k + 0) * 128 + n];
        float w1 = W[(k + 1) * 128 + n];
        __nv_bfloat162 hi = __floats2bfloat162_rn(w0, w1);
        float l0 = w0 - __bfloat162float(hi.x);
        float l1 = w1 - __bfloat162float(hi.y);
        __nv_bfloat162 lo = __floats2bfloat162_rn(l0, l1);
        outHi[n * 64 + (k >> 1)] = b2u(hi);
        outLo[n * 64 + (k >> 1)] = b2u(lo);
    }
}

// ---------------- bf16x3 tensor-core GEMM via mma.sync: C[M,128] = A[M,128] @ W[128,128]
// M-tile = 64 rows -> 104448B smem -> 2 CTAs/SM (load/compute overlap across CTAs).
// D = Ahi*Bhi + Ahi*Blo + Alo*Bhi (fp32 accum). B pre-split/transposed by k_prep_w.
#define BSTRIDE 136                       // halves per smem row (272B -> conflict-free ldmatrix)
#define SOFF_ALO (64 * BSTRIDE)
#define SOFF_BHI (128 * BSTRIDE)
#define SOFF_BLO (256 * BSTRIDE)
#define SMEM_GEMM (384 * BSTRIDE * 2)     // 104448 bytes

__global__ __launch_bounds__(256, 2)
void gemm_mma(const float* __restrict__ A, const uint32_t* __restrict__ BHi,
              const uint32_t* __restrict__ BLo, float* __restrict__ C, int M) {
    extern __shared__ __align__(16) uint8_t smraw[];
    __nv_bfloat16* sAhi = (__nv_bfloat16*)smraw;
    __nv_bfloat16* sAlo = sAhi + SOFF_ALO;
    __nv_bfloat16* sBhi = sAhi + SOFF_BHI;
    __nv_bfloat16* sBlo = sAhi + SOFF_BLO;

    const int tid = threadIdx.x;
    const int w = tid >> 5, lane = tid & 31;
    const int rbase = blockIdx.x * 64;

    // B: copy pre-split images (2048 uint4 each) into padded smem rows
    const uint4* bh4 = (const uint4*)BHi;
    const uint4* bl4 = (const uint4*)BLo;
    #pragma unroll
    for (int it = 0; it < 16; it++) {
        int i = it * 256 + tid;           // 0..4095
        int j = i & 2047;
        int n = j >> 4, c = j & 15;
        __nv_bfloat16* dst = (i < 2048) ? sBhi : sBlo;
        *(uint4*)(dst + n * BSTRIDE + c * 8) = (i < 2048) ? bh4[j] : bl4[j];
    }
    // A: coalesced fp32 load -> hi/lo bf16 split -> padded smem (64 rows)
    const float4* A4 = (const float4*)A;
    #pragma unroll
    for (int it = 0; it < 8; it++) {
        int f = it * 256 + tid;           // 0..2047
        int row = f >> 5, c4 = f & 31;
        int gr = rbase + row;
        float4 v = make_float4(0.f, 0.f, 0.f, 0.f);
        if (gr < M) v = A4[gr * 32 + c4];
        __nv_bfloat162 h01 = __floats2bfloat162_rn(v.x, v.y);
        __nv_bfloat162 h23 = __floats2bfloat162_rn(v.z, v.w);
        __nv_bfloat162 l01 = __floats2bfloat162_rn(v.x - __bfloat162float(h01.x),
                                                   v.y - __bfloat162float(h01.y));
        __nv_bfloat162 l23 = __floats2bfloat162_rn(v.z - __bfloat162float(h23.x),
                                                   v.w - __bfloat162float(h23.y));
        *(uint2*)(sAhi + row * BSTRIDE + c4 * 4) = make_uint2(b2u(h01), b2u(h23));
        *(uint2*)(sAlo + row * BSTRIDE + c4 * 4) = make_uint2(b2u(l01), b2u(l23));
    }
    __syncthreads();

    // warp tile: m16 (row wm = w>>1) x n64 (col group wn = w&1)
    const int wm = w >> 1, wn = w & 1;
    const int quad = lane >> 3, l = lane & 7;
    const uint32_t aoff = (uint32_t)(((wm * 16 + (quad & 1) * 8 + l) * BSTRIDE + (quad >> 1) * 8) * 2);
    const uint32_t boff = (uint32_t)((((quad >> 1) * 8 + l) * BSTRIDE + (quad & 1) * 8) * 2);
    const uint32_t aHiA = smem_u32(sAhi) + aoff;
    const uint32_t aLoA = smem_u32(sAlo) + aoff;
    const uint32_t bHiA = smem_u32(sBhi) + boff + (uint32_t)(wn * 64 * BSTRIDE * 2);
    const uint32_t bLoA = smem_u32(sBlo) + boff + (uint32_t)(wn * 64 * BSTRIDE * 2);

    float acc[8][4];
    #pragma unroll
    for (int i = 0; i < 8; i++)
        #pragma unroll
        for (int j = 0; j < 4; j++) acc[i][j] = 0.f;

    #pragma unroll 1
    for (int ks = 0; ks < 8; ks++) {
        uint32_t ah[4], al[4];
        ldsm_x4(aHiA + ks * 32, ah[0], ah[1], ah[2], ah[3]);
        ldsm_x4(aLoA + ks * 32, al[0], al[1], al[2], al[3]);
        #pragma unroll
        for (int np = 0; np < 4; np++) {
            uint32_t bh[4], bl[4];
            uint32_t o = (uint32_t)(np * 16 * BSTRIDE * 2 + ks * 32);
            ldsm_x4(bHiA + o, bh[0], bh[1], bh[2], bh[3]);
            ldsm_x4(bLoA + o, bl[0], bl[1], bl[2], bl[3]);
            mma16816(acc[2 * np],     ah, bh);
            mma16816(acc[2 * np + 1], ah, bh + 2);
            mma16816(acc[2 * np],     ah, bl);
            mma16816(acc[2 * np + 1], ah, bl + 2);
            mma16816(acc[2 * np],     al, bh);
            mma16816(acc[2 * np + 1], al, bh + 2);
        }
    }

    // Epilogue: direct float2 stores
    const int r0 = rbase + wm * 16 + (lane >> 2);
    const int cn = wn * 64 + (lane & 3) * 2;
    #pragma unroll
    for (int j = 0; j < 8; j++) {
        if (r0 < M)     *(float2*)&C[r0 * 128 + cn + j * 8]       = make_float2(acc[j][0], acc[j][1]);
        if (r0 + 8 < M) *(float2*)&C[(r0 + 8) * 128 + cn + j * 8] = make_float2(acc[j][2], acc[j][3]);
    }
}

// ---------------- per-edge gate: alpha = sigmoid(wa . relu(U[n]+Vr[r+1]+Qb[b]) + wa_b)
// written to g_alphaP at the edge's sorted position
__global__ __launch_bounds__(256)
void k_alpha(const int* __restrict__ facts, const float* __restrict__ wa_w,
             const float* __restrict__ wa_b, int E) {
    int wid = (blockIdx.x * blockDim.x + threadIdx.x) >> 5;
    int lane = threadIdx.x & 31;
    if (wid >= E) return;
    int2 bn = *(const int2*)(facts + wid * 6);      // (b, n)
    int2 hr = *(const int2*)(facts + wid * 6 + 2);  // (h, r)
    int b = bn.x, n = bn.y, r = hr.y;

    const float4* U4 = (const float4*)g_U;
    const float4* V4 = (const float4*)g_Vr;
    const float4* Q4 = (const float4*)g_Qb;
    const float4* W4 = (const float4*)wa_w;

    float4 u = U4[n * 32 + lane];
    float4 v = V4[(r + 1) * 32 + lane];
    float4 q = Q4[b * 32 + lane];
    float4 w = W4[lane];

    float s = fmaxf(u.x + v.x + q.x, 0.f) * w.x
            + fmaxf(u.y + v.y + q.y, 0.f) * w.y
            + fmaxf(u.z + v.z + q.z, 0.f) * w.z
            + fmaxf(u.w + v.w + q.w, 0.f) * w.w;
    s += __shfl_xor_sync(0xffffffffu, s, 16);
    s += __shfl_xor_sync(0xffffffffu, s, 8);
    s += __shfl_xor_sync(0xffffffffu, s, 4);
    s += __shfl_xor_sync(0xffffffffu, s, 2);
    s += __shfl_xor_sync(0xffffffffu, s, 1);
    if (lane == 0) {
        float x = s + wa_b[0];
        g_alphaP[g_pos[wid]] = 1.f / (1.f + __expf(-x));
    }
}

// ---------------- per-segment aggregation: sequential edge records, pipelined gather ----------------
__global__ __launch_bounds__(256)
void k_agg(const float* __restrict__ hidden, const float* __restrict__ rel, int T) {
    int seg = (blockIdx.x * blockDim.x + threadIdx.x) >> 5;
    int lane = threadIdx.x & 31;
    if (seg >= T) return;
    int s0 = g_segstart[seg];
    int s1 = g_segstart[seg + 1];

    const float4* H4 = (const float4*)hidden;
    const float4* R4 = (const float4*)rel;
    float4 acc = make_float4(0.f, 0.f, 0.f, 0.f);

    int k = s0;
    int2 nr = make_int2(0, 0);
    float a = 0.f;
    if (k < s1) { nr = g_edgeNR[k]; a = g_alphaP[k]; }
    while (k < s1) {
        int kn = k + 1;
        int2 nrn = make_int2(0, 0);
        float an = 0.f;
        if (kn < s1) { nrn = g_edgeNR[kn]; an = g_alphaP[kn]; }  // prefetch next (sequential)
        float4 h  = H4[nr.x * 32 + lane];
        float4 hr = R4[nr.y * 32 + lane];
        acc.x = fmaf(a, h.x + hr.x, acc.x);
        acc.y = fmaf(a, h.y + hr.y, acc.y);
        acc.z = fmaf(a, h.z + hr.z, acc.z);
        acc.w = fmaf(a, h.w + hr.w, acc.w);
        nr = nrn; a = an; k = kn;
    }
    ((float4*)g_AGG)[seg * 32 + lane] = acc;
}

// ---------------- launch ----------------
extern "C" void kernel_launch(void* const* d_in, const int* in_sizes, int n_in,
                              void* d_out, int out_size) {
    const float* hidden    = (const float*)d_in[0];
    const float* rel_table = (const float*)d_in[1];
    const float* Ws        = (const float*)d_in[2];
    const float* Wr        = (const float*)d_in[3];
    const float* Wqr_w     = (const float*)d_in[4];
    const float* Wqr_b     = (const float*)d_in[5];
    const float* wa_w      = (const float*)d_in[6];
    const float* wa_b      = (const float*)d_in[7];
    const float* Wh        = (const float*)d_in[8];
    const int*   query_rel = (const int*)d_in[9];
    const int*   facts     = (const int*)d_in[10];
    const int*   tail      = (const int*)d_in[11];

    const int E  = in_sizes[11];          // 1,000,000
    const int T  = in_sizes[12];          // 100,000
    const int N  = in_sizes[0] / DDIM;    // 200,000
    const int B  = in_sizes[9];           // 512
    const int NR = in_sizes[1] / DDIM;    // 481
    float* out = (float*)d_out;

    cudaFuncSetAttribute((const void*)gemm_mma,
                         cudaFuncAttributeMaxDynamicSharedMemorySize, SMEM_GEMM);

    float* d_U;   cudaGetSymbolAddress((void**)&d_U, g_U);
    float* d_AGG; cudaGetSymbolAddress((void**)&d_AGG, g_AGG);
    int* d_segcnt; cudaGetSymbolAddress((void**)&d_segcnt, g_segcnt);
    uint32_t *d_WsHi, *d_WsLo, *d_WhHi, *d_WhLo;
    cudaGetSymbolAddress((void**)&d_WsHi, g_WsHi);
    cudaGetSymbolAddress((void**)&d_WsLo, g_WsLo);
    cudaGetSymbolAddress((void**)&d_WhHi, g_WhHi);
    cudaGetSymbolAddress((void**)&d_WhLo, g_WhLo);

    // order chosen so launch index 3 (the ncu -s window) = gemm_mma (GEMM1)
    k_prep_w<<<1, 128>>>(Ws, d_WsHi, d_WsLo);                              // 0
    k_vr<<<NR, DDIM>>>(rel_table, Wr);                                     // 1
    k_qb<<<B, DDIM>>>(rel_table, Wqr_w, Wqr_b, query_rel);                 // 2
    gemm_mma<<<(N + 63) / 64, 256, SMEM_GEMM>>>(hidden, d_WsHi, d_WsLo, d_U, N);  // 3 <- profiled

    // counting sort of edges by tail segment
    k_zero_int<<<(T + 255) / 256, 256>>>(d_segcnt, T);                     // 4
    k_hist<<<(E + 255) / 256, 256>>>(tail, E);                             // 5
    int nb = (T + 1023) / 1024;
    k_scanA<<<nb, 1024>>>(T);                                              // 6
    k_scanB<<<1, 128>>>(nb);                                               // 7
    k_scanC<<<nb, 1024>>>(T, E);                                           // 8
    k_scatter<<<(E + 255) / 256, 256>>>(tail, facts, E);                   // 9

    // per-edge gates (needs gemm1 + vr + qb + scatter)
    k_alpha<<<(E + 7) / 8, 256>>>(facts, wa_w, wa_b, E);                   // 10

    // segment aggregation (sequential edge records, no indirection)
    k_agg<<<(T + 7) / 8, 256>>>(hidden, rel_table, T);                     // 11

    // output projection
    k_prep_w<<<1, 128>>>(Wh, d_WhHi, d_WhLo);                              // 12
    gemm_mma<<<(T + 63) / 64, 256, SMEM_GEMM>>>(d_AGG, d_WhHi, d_WhLo, out, T);   // 13
}

// round 5
// speedup vs baseline: 1.4569x; 1.0146x over previous
#include <cuda_runtime.h>
#include <cuda_bf16.h>
#include <cstdint>

// Problem constants (fixed for this dataset instance)
#define EMAX 1000000
#define DDIM 128
#define NMAX 200000
#define BMAX 512
#define NRMAX 481      // 2R+1
#define TMAX 100000

// ---------------- device scratch (static globals; no allocation) ----------------
__device__ float g_U[NMAX * DDIM];        // hidden @ Ws
__device__ float g_Vr[NRMAX * DDIM];      // rel_table @ Wr
__device__ float g_Qb[BMAX * DDIM];       // rel_table[query_rel+1] @ Wqr_w + b
__device__ float g_AGG[TMAX * DDIM];      // segment sums
// tail sort
__device__ int   g_segcnt[TMAX];
__device__ int   g_segstart[TMAX + 1];
__device__ int   g_cursor[TMAX];
__device__ int   g_part[256];
__device__ int   g_pos[EMAX];             // edge -> tail-sorted position
__device__ int4  g_aggRec[EMAX];          // tail-sorted: (n, r+1, alpha_bits, pad)
// node sort
__device__ int   g_ncnt[NMAX];
__device__ int   g_nstart[NMAX + 1];
__device__ int   g_ncursor[NMAX];
__device__ int   g_partN[256];
__device__ int4  g_eRec[EMAX];            // n-sorted: (b, r+1, tail_pos, pad)
// pre-split transposed weight images Wt[n][k] (bf16 hi/lo, packed as uint32 = 2 halves)
__device__ uint32_t g_WsHi[8192];
__device__ uint32_t g_WsLo[8192];
__device__ uint32_t g_WhHi[8192];
__device__ uint32_t g_WhLo[8192];

__device__ __forceinline__ uint32_t smem_u32(const void* p) {
    uint32_t a;
    asm("{ .reg .u64 t; cvta.to.shared.u64 t, %1; cvt.u32.u64 %0, t; }" : "=r"(a) : "l"(p));
    return a;
}
__device__ __forceinline__ uint32_t b2u(__nv_bfloat162 h) { return *reinterpret_cast<uint32_t*>(&h); }

__device__ __forceinline__ void ldsm_x4(uint32_t addr, uint32_t& r0, uint32_t& r1,
                                        uint32_t& r2, uint32_t& r3) {
    asm volatile("ldmatrix.sync.aligned.m8n8.x4.shared.b16 {%0,%1,%2,%3}, [%4];"
                 : "=r"(r0), "=r"(r1), "=r"(r2), "=r"(r3) : "r"(addr));
}
__device__ __forceinline__ void mma16816(float* d, const uint32_t* a, const uint32_t* b) {
    asm volatile(
        "mma.sync.aligned.m16n8k16.row.col.f32.bf16.bf16.f32 "
        "{%0,%1,%2,%3}, {%4,%5,%6,%7}, {%8,%9}, {%0,%1,%2,%3};"
        : "+f"(d[0]), "+f"(d[1]), "+f"(d[2]), "+f"(d[3])
        : "r"(a[0]), "r"(a[1]), "r"(a[2]), "r"(a[3]), "r"(b[0]), "r"(b[1]));
}

// ---------------- generic counting-sort kernels ----------------
__global__ void k_zero_int(int* p, int n) {
    int i = blockIdx.x * blockDim.x + threadIdx.x;
    if (i < n) p[i] = 0;
}

__global__ void k_hist_tail(const int* __restrict__ tail, int* __restrict__ cnt, int E) {
    int e = blockIdx.x * blockDim.x + threadIdx.x;
    if (e < E) atomicAdd(&cnt[tail[e]], 1);
}

__global__ void k_hist_n(const int* __restrict__ facts, int* __restrict__ cnt, int E) {
    int e = blockIdx.x * blockDim.x + threadIdx.x;
    if (e < E) {
        int2 bn = *(const int2*)(facts + e * 6);
        atomicAdd(&cnt[bn.y], 1);
    }
}

__global__ void k_scanA(const int* __restrict__ cnt, int* __restrict__ start,
                        int* __restrict__ part, int T) {
    __shared__ int s[1024];
    int i = blockIdx.x * 1024 + threadIdx.x;
    int v = (i < T) ? cnt[i] : 0;
    s[threadIdx.x] = v;
    __syncthreads();
    for (int off = 1; off < 1024; off <<= 1) {
        int x = (threadIdx.x >= off) ? s[threadIdx.x - off] : 0;
        __syncthreads();
        s[threadIdx.x] += x;
        __syncthreads();
    }
    if (i < T) start[i] = s[threadIdx.x] - v;  // block-local exclusive
    if (threadIdx.x == 1023) part[blockIdx.x] = s[1023];
}

__global__ void k_scanB(int* __restrict__ part, int nb) {
    __shared__ int s[256];
    int i = threadIdx.x;
    int v = (i < nb) ? part[i] : 0;
    s[i] = v;
    __syncthreads();
    for (int off = 1; off < 256; off <<= 1) {
        int x = (i >= off) ? s[i - off] : 0;
        __syncthreads();
        s[i] += x;
        __syncthreads();
    }
    if (i < nb) part[i] = s[i] - v;  // exclusive
}

__global__ void k_scanC(int* __restrict__ start, int* __restrict__ cursor,
                        const int* __restrict__ part, int T, int E) {
    int i = blockIdx.x * 1024 + threadIdx.x;
    if (i < T) {
        int v = start[i] + part[blockIdx.x];
        start[i] = v;
        cursor[i] = v;
    }
    if (i == 0) start[T] = E;
}

// tail scatter: writes (n, r+1) into aggRec at the sorted position; records pos per edge
__global__ void k_scatter_tail(const int* __restrict__ tail, const int* __restrict__ facts, int E) {
    int e = blockIdx.x * blockDim.x + threadIdx.x;
    if (e < E) {
        int2 bn = *(const int2*)(facts + e * 6);      // (b, n)
        int2 hr = *(const int2*)(facts + e * 6 + 2);  // (h, r)
        int p = atomicAdd(&g_cursor[tail[e]], 1);
        *(int2*)&g_aggRec[p] = make_int2(bn.y, hr.y + 1);
        g_pos[e] = p;
    }
}

// node scatter: writes (b, r+1, tail_pos) into eRec at the n-sorted position
__global__ void k_scatter_n(const int* __restrict__ facts, int E) {
    int e = blockIdx.x * blockDim.x + threadIdx.x;
    if (e < E) {
        int2 bn = *(const int2*)(facts + e * 6);      // (b, n)
        int2 hr = *(const int2*)(facts + e * 6 + 2);  // (h, r)
        int q = atomicAdd(&g_ncursor[bn.y], 1);
        g_eRec[q] = make_int4(bn.x, hr.y + 1, g_pos[e], 0);
    }
}

// ---------------- tiny projections ----------------
__global__ void k_vr(const float* __restrict__ rel, const float* __restrict__ Wr) {
    __shared__ float row[DDIM];
    int r = blockIdx.x, j = threadIdx.x;
    row[j] = rel[r * DDIM + j];
    __syncthreads();
    float s = 0.f;
    #pragma unroll 8
    for (int k = 0; k < DDIM; k++) s = fmaf(row[k], Wr[k * DDIM + j], s);
    g_Vr[r * DDIM + j] = s;
}

__global__ void k_qb(const float* __restrict__ rel, const float* __restrict__ W,
                     const float* __restrict__ bias, const int* __restrict__ qrel) {
    __shared__ float row[DDIM];
    int b = blockIdx.x, j = threadIdx.x;
    int r = qrel[b] + 1;
    row[j] = rel[r * DDIM + j];
    __syncthreads();
    float s = bias[j];
    #pragma unroll 8
    for (int k = 0; k < DDIM; k++) s = fmaf(row[k], W[k * DDIM + j], s);
    g_Qb[b * DDIM + j] = s;
}

// ---------------- weight prep: split fp32 W[k][n] -> bf16 hi/lo, transposed Wt[n][k] ----------------
__global__ void k_prep_w(const float* __restrict__ W,
                         uint32_t* __restrict__ outHi, uint32_t* __restrict__ outLo) {
    int n = threadIdx.x;  // 128 threads, one output row (N dim) each
    #pragma unroll 4
    for (int k = 0; k < 128; k += 2) {
        float w0 = W[(k + 0) * 128 + n];
        float w1 = W[(k + 1) * 128 + n];
        __nv_bfloat162 hi = __floats2bfloat162_rn(w0, w1);
        float l0 = w0 - __bfloat162float(hi.x);
        float l1 = w1 - __bfloat162float(hi.y);
        __nv_bfloat162 lo = __floats2bfloat162_rn(l0, l1);
        outHi[n * 64 + (k >> 1)] = b2u(hi);
        outLo[n * 64 + (k >> 1)] = b2u(lo);
    }
}

// ---------------- bf16x3 tensor-core GEMM via mma.sync: C[M,128] = A[M,128] @ W[128,128]
// M-tile 64 rows, 2 CTAs/SM, warp tile m32 x n32 (8 LDSM.x4 -> 24 MMA per k-step).
// D = Ahi*Bhi + Ahi*Blo + Alo*Bhi (fp32 accum). B pre-split/transposed by k_prep_w.
#define BSTRIDE 136                       // halves per smem row (272B -> conflict-free ldmatrix)
#define SOFF_ALO (64 * BSTRIDE)
#define SOFF_BHI (128 * BSTRIDE)
#define SOFF_BLO (256 * BSTRIDE)
#define SMEM_GEMM (384 * BSTRIDE * 2)     // 104448 bytes

__global__ __launch_bounds__(256, 2)
void gemm_mma(const float* __restrict__ A, const uint32_t* __restrict__ BHi,
              const uint32_t* __restrict__ BLo, float* __restrict__ C, int M) {
    extern __shared__ __align__(16) uint8_t smraw[];
    __nv_bfloat16* sAhi = (__nv_bfloat16*)smraw;
    __nv_bfloat16* sAlo = sAhi + SOFF_ALO;
    __nv_bfloat16* sBhi = sAhi + SOFF_BHI;
    __nv_bfloat16* sBlo = sAhi + SOFF_BLO;

    const int tid = threadIdx.x;
    const int w = tid >> 5, lane = tid & 31;
    const int rbase = blockIdx.x * 64;

    // B: copy pre-split images (2048 uint4 each) into padded smem rows
    const uint4* bh4 = (const uint4*)BHi;
    const uint4* bl4 = (const uint4*)BLo;
    #pragma unroll
    for (int it = 0; it < 16; it++) {
        int i = it * 256 + tid;           // 0..4095
        int j = i & 2047;
        int n = j >> 4, c = j & 15;
        __nv_bfloat16* dst = (i < 2048) ? sBhi : sBlo;
        *(uint4*)(dst + n * BSTRIDE + c * 8) = (i < 2048) ? bh4[j] : bl4[j];
    }
    // A: coalesced fp32 load -> hi/lo bf16 split -> padded smem (64 rows)
    const float4* A4 = (const float4*)A;
    #pragma unroll
    for (int it = 0; it < 8; it++) {
        int f = it * 256 + tid;           // 0..2047
        int row = f >> 5, c4 = f & 31;
        int gr = rbase + row;
        float4 v = make_float4(0.f, 0.f, 0.f, 0.f);
        if (gr < M) v = A4[gr * 32 + c4];
        __nv_bfloat162 h01 = __floats2bfloat162_rn(v.x, v.y);
        __nv_bfloat162 h23 = __floats2bfloat162_rn(v.z, v.w);
        __nv_bfloat162 l01 = __floats2bfloat162_rn(v.x - __bfloat162float(h01.x),
                                                   v.y - __bfloat162float(h01.y));
        __nv_bfloat162 l23 = __floats2bfloat162_rn(v.z - __bfloat162float(h23.x),
                                                   v.w - __bfloat162float(h23.y));
        *(uint2*)(sAhi + row * BSTRIDE + c4 * 4) = make_uint2(b2u(h01), b2u(h23));
        *(uint2*)(sAlo + row * BSTRIDE + c4 * 4) = make_uint2(b2u(l01), b2u(l23));
    }
    __syncthreads();

    // warp tile: m32 (wm = w>>2) x n32 (wn = w&3)
    const int wm = w >> 2, wn = w & 3;
    const int quad = lane >> 3, l = lane & 7;
    const uint32_t aoff0 = (uint32_t)(((wm * 32 + 0  + (quad & 1) * 8 + l) * BSTRIDE + (quad >> 1) * 8) * 2);
    const uint32_t aoff1 = (uint32_t)(((wm * 32 + 16 + (quad & 1) * 8 + l) * BSTRIDE + (quad >> 1) * 8) * 2);
    const uint32_t boff0 = (uint32_t)(((wn * 32 + 0  + (quad >> 1) * 8 + l) * BSTRIDE + (quad & 1) * 8) * 2);
    const uint32_t boff1 = (uint32_t)(((wn * 32 + 16 + (quad >> 1) * 8 + l) * BSTRIDE + (quad & 1) * 8) * 2);
    const uint32_t sA = smem_u32(sAhi), sAl = smem_u32(sAlo);
    const uint32_t sB = smem_u32(sBhi), sBl = smem_u32(sBlo);
    const uint32_t aHi0 = sA + aoff0, aHi1 = sA + aoff1;
    const uint32_t aLo0 = sAl + aoff0, aLo1 = sAl + aoff1;
    const uint32_t bHi0 = sB + boff0, bHi1 = sB + boff1;
    const uint32_t bLo0 = sBl + boff0, bLo1 = sBl + boff1;

    float acc[2][4][4];
    #pragma unroll
    for (int i = 0; i < 2; i++)
        #pragma unroll
        for (int j = 0; j < 4; j++)
            #pragma unroll
            for (int q = 0; q < 4; q++) acc[i][j][q] = 0.f;

    #pragma unroll 1
    for (int ks = 0; ks < 8; ks++) {
        const uint32_t ko = (uint32_t)(ks * 32);
        uint32_t ah0[4], ah1[4], al0[4], al1[4];
        uint32_t bh0[4], bh1[4], bl0[4], bl1[4];
        ldsm_x4(aHi0 + ko, ah0[0], ah0[1], ah0[2], ah0[3]);
        ldsm_x4(aHi1 + ko, ah1[0], ah1[1], ah1[2], ah1[3]);
        ldsm_x4(bHi0 + ko, bh0[0], bh0[1], bh0[2], bh0[3]);
        ldsm_x4(bHi1 + ko, bh1[0], bh1[1], bh1[2], bh1[3]);
        ldsm_x4(aLo0 + ko, al0[0], al0[1], al0[2], al0[3]);
        ldsm_x4(aLo1 + ko, al1[0], al1[1], al1[2], al1[3]);
        ldsm_x4(bLo0 + ko, bl0[0], bl0[1], bl0[2], bl0[3]);
        ldsm_x4(bLo1 + ko, bl1[0], bl1[1], bl1[2], bl1[3]);

        // pass 1: Ahi * Bhi
        mma16816(acc[0][0], ah0, bh0); mma16816(acc[0][1], ah0, bh0 + 2);
        mma16816(acc[0][2], ah0, bh1); mma16816(acc[0][3], ah0, bh1 + 2);
        mma16816(acc[1][0], ah1, bh0); mma16816(acc[1][1], ah1, bh0 + 2);
        mma16816(acc[1][2], ah1, bh1); mma16816(acc[1][3], ah1, bh1 + 2);
        // pass 2: Ahi * Blo
        mma16816(acc[0][0], ah0, bl0); mma16816(acc[0][1], ah0, bl0 + 2);
        mma16816(acc[0][2], ah0, bl1); mma16816(acc[0][3], ah0, bl1 + 2);
        mma16816(acc[1][0], ah1, bl0); mma16816(acc[1][1], ah1, bl0 + 2);
        mma16816(acc[1][2], ah1, bl1); mma16816(acc[1][3], ah1, bl1 + 2);
        // pass 3: Alo * Bhi
        mma16816(acc[0][0], al0, bh0); mma16816(acc[0][1], al0, bh0 + 2);
        mma16816(acc[0][2], al0, bh1); mma16816(acc[0][3], al0, bh1 + 2);
        mma16816(acc[1][0], al1, bh0); mma16816(acc[1][1], al1, bh0 + 2);
        mma16816(acc[1][2], al1, bh1); mma16816(acc[1][3], al1, bh1 + 2);
    }

    // Epilogue: direct float2 stores
    #pragma unroll
    for (int i = 0; i < 2; i++) {
        const int r0 = rbase + wm * 32 + i * 16 + (lane >> 2);
        #pragma unroll
        for (int jn = 0; jn < 4; jn++) {
            const int cn = wn * 32 + jn * 8 + (lane & 3) * 2;
            if (r0 < M)     *(float2*)&C[r0 * 128 + cn]       = make_float2(acc[i][jn][0], acc[i][jn][1]);
            if (r0 + 8 < M) *(float2*)&C[(r0 + 8) * 128 + cn] = make_float2(acc[i][jn][2], acc[i][jn][3]);
        }
    }
}

// ---------------- per-node gate kernel: warp per node, U[n] + wa cached in registers ----------------
// alpha = sigmoid(wa . relu(U[n]+Vr[r+1]+Qb[b]) + wa_b), written into aggRec[tail_pos].z
__global__ __launch_bounds__(256)
void k_alpha(const float* __restrict__ wa_w, const float* __restrict__ wa_b, int N) {
    int seg = (blockIdx.x * blockDim.x + threadIdx.x) >> 5;
    int lane = threadIdx.x & 31;
    if (seg >= N) return;
    int s0 = g_nstart[seg];
    int s1 = g_nstart[seg + 1];
    if (s0 == s1) return;

    const float4* U4 = (const float4*)g_U;
    const float4* V4 = (const float4*)g_Vr;
    const float4* Q4 = (const float4*)g_Qb;

    float4 u = U4[seg * 32 + lane];
    float4 w = ((const float4*)wa_w)[lane];
    float wb = wa_b[0];

    for (int k = s0; k < s1; k++) {
        int4 rec = g_eRec[k];             // (b, r+1, tail_pos)
        float4 v = V4[rec.y * 32 + lane];
        float4 q = Q4[rec.x * 32 + lane];
        float s = fmaxf(u.x + v.x + q.x, 0.f) * w.x
                + fmaxf(u.y + v.y + q.y, 0.f) * w.y
                + fmaxf(u.z + v.z + q.z, 0.f) * w.z
                + fmaxf(u.w + v.w + q.w, 0.f) * w.w;
        s += __shfl_xor_sync(0xffffffffu, s, 16);
        s += __shfl_xor_sync(0xffffffffu, s, 8);
        s += __shfl_xor_sync(0xffffffffu, s, 4);
        s += __shfl_xor_sync(0xffffffffu, s, 2);
        s += __shfl_xor_sync(0xffffffffu, s, 1);
        if (lane == 0) {
            float x = s + wb;
            float a = 1.f / (1.f + __expf(-x));
            ((int*)&g_aggRec[rec.z])[2] = __float_as_int(a);
        }
    }
}

// ---------------- per-segment aggregation: single 16B record per edge, pipelined gather ----------------
__global__ __launch_bounds__(256)
void k_agg(const float* __restrict__ hidden, const float* __restrict__ rel, int T) {
    int seg = (blockIdx.x * blockDim.x + threadIdx.x) >> 5;
    int lane = threadIdx.x & 31;
    if (seg >= T) return;
    int s0 = g_segstart[seg];
    int s1 = g_segstart[seg + 1];

    const float4* H4 = (const float4*)hidden;
    const float4* R4 = (const float4*)rel;
    float4 acc = make_float4(0.f, 0.f, 0.f, 0.f);

    int k = s0;
    int4 rec = make_int4(0, 0, 0, 0);
    if (k < s1) rec = g_aggRec[k];
    while (k < s1) {
        int kn = k + 1;
        int4 recn = make_int4(0, 0, 0, 0);
        if (kn < s1) recn = g_aggRec[kn];  // prefetch next (sequential)
        float a = __int_as_float(rec.z);
        float4 h  = H4[rec.x * 32 + lane];
        float4 hr = R4[rec.y * 32 + lane];
        acc.x = fmaf(a, h.x + hr.x, acc.x);
        acc.y = fmaf(a, h.y + hr.y, acc.y);
        acc.z = fmaf(a, h.z + hr.z, acc.z);
        acc.w = fmaf(a, h.w + hr.w, acc.w);
        rec = recn; k = kn;
    }
    ((float4*)g_AGG)[seg * 32 + lane] = acc;
}

// ---------------- launch ----------------
extern "C" void kernel_launch(void* const* d_in, const int* in_sizes, int n_in,
                              void* d_out, int out_size) {
    const float* hidden    = (const float*)d_in[0];
    const float* rel_table = (const float*)d_in[1];
    const float* Ws        = (const float*)d_in[2];
    const float* Wr        = (const float*)d_in[3];
    const float* Wqr_w     = (const float*)d_in[4];
    const float* Wqr_b     = (const float*)d_in[5];
    const float* wa_w      = (const float*)d_in[6];
    const float* wa_b      = (const float*)d_in[7];
    const float* Wh        = (const float*)d_in[8];
    const int*   query_rel = (const int*)d_in[9];
    const int*   facts     = (const int*)d_in[10];
    const int*   tail      = (const int*)d_in[11];

    const int E  = in_sizes[11];          // 1,000,000
    const int T  = in_sizes[12];          // 100,000
    const int N  = in_sizes[0] / DDIM;    // 200,000
    const int B  = in_sizes[9];           // 512
    const int NR = in_sizes[1] / DDIM;    // 481
    float* out = (float*)d_out;

    cudaFuncSetAttribute((const void*)gemm_mma,
                         cudaFuncAttributeMaxDynamicSharedMemorySize, SMEM_GEMM);

    float* d_U;   cudaGetSymbolAddress((void**)&d_U, g_U);
    float* d_AGG; cudaGetSymbolAddress((void**)&d_AGG, g_AGG);
    int *d_segcnt, *d_segstart, *d_cursor, *d_part;
    int *d_ncnt, *d_nstart, *d_ncursor, *d_partN;
    cudaGetSymbolAddress((void**)&d_segcnt, g_segcnt);
    cudaGetSymbolAddress((void**)&d_segstart, g_segstart);
    cudaGetSymbolAddress((void**)&d_cursor, g_cursor);
    cudaGetSymbolAddress((void**)&d_part, g_part);
    cudaGetSymbolAddress((void**)&d_ncnt, g_ncnt);
    cudaGetSymbolAddress((void**)&d_nstart, g_nstart);
    cudaGetSymbolAddress((void**)&d_ncursor, g_ncursor);
    cudaGetSymbolAddress((void**)&d_partN, g_partN);
    uint32_t *d_WsHi, *d_WsLo, *d_WhHi, *d_WhLo;
    cudaGetSymbolAddress((void**)&d_WsHi, g_WsHi);
    cudaGetSymbolAddress((void**)&d_WsLo, g_WsLo);
    cudaGetSymbolAddress((void**)&d_WhHi, g_WhHi);
    cudaGetSymbolAddress((void**)&d_WhLo, g_WhLo);

    // order chosen so the ncu capture window lands on gemm_mma (GEMM1) at index 3
    k_prep_w<<<1, 128>>>(Ws, d_WsHi, d_WsLo);                              // 0
    k_vr<<<NR, DDIM>>>(rel_table, Wr);                                     // 1
    k_qb<<<B, DDIM>>>(rel_table, Wqr_w, Wqr_b, query_rel);                 // 2
    gemm_mma<<<(N + 63) / 64, 256, SMEM_GEMM>>>(hidden, d_WsHi, d_WsLo, d_U, N);  // 3 <- profiled

    // counting sort by tail segment
    int nbT = (T + 1023) / 1024;
    k_zero_int<<<(T + 255) / 256, 256>>>(d_segcnt, T);
    k_hist_tail<<<(E + 255) / 256, 256>>>(tail, d_segcnt, E);
    k_scanA<<<nbT, 1024>>>(d_segcnt, d_segstart, d_part, T);
    k_scanB<<<1, 256>>>(d_part, nbT);
    k_scanC<<<nbT, 1024>>>(d_segstart, d_cursor, d_part, T, E);
    k_scatter_tail<<<(E + 255) / 256, 256>>>(tail, facts, E);

    // counting sort by node n (needs g_pos from tail scatter)
    int nbN = (N + 1023) / 1024;
    k_zero_int<<<(N + 255) / 256, 256>>>(d_ncnt, N);
    k_hist_n<<<(E + 255) / 256, 256>>>(facts, d_ncnt, E);
    k_scanA<<<nbN, 1024>>>(d_ncnt, d_nstart, d_partN, N);
    k_scanB<<<1, 256>>>(d_partN, nbN);
    k_scanC<<<nbN, 1024>>>(d_nstart, d_ncursor, d_partN, N, E);
    k_scatter_n<<<(E + 255) / 256, 256>>>(facts, E);

    // per-node gates (warp per node, U in registers)
    k_alpha<<<(N + 7) / 8, 256>>>(wa_w, wa_b, N);

    // segment aggregation (single 16B record per edge)
    k_agg<<<(T + 7) / 8, 256>>>(hidden, rel_table, T);

    // output projection
    k_prep_w<<<1, 128>>>(Wh, d_WhHi, d_WhLo);
    gemm_mma<<<(T + 63) / 64, 256, SMEM_GEMM>>>(d_AGG, d_WhHi, d_WhLo, out, T);
}